// round 1
// baseline (speedup 1.0000x reference)
#include <cuda_runtime.h>
#include <cuda_bf16.h>
#include <cstddef>

// Problem constants (fixed shapes per reference):
//   NX=432, NY=496, C=64, B=4, P=40000
#define NXc 432
#define NYc 496
#define Cc  64
#define Bc  4

// Scratch: inverse index grid, idx[b*NY*NX + y*NX + x] = pillar id or -1.
// 4*496*432 ints = ~3.4 MB as a __device__ global (allocation-free).
__device__ int g_idx[Bc * NYc * NXc];
__device__ int g_is64;

// Detect coord dtype at runtime: int64 little-endian small nonneg values have
// all-zero high words -> odd int32 positions all zero across first 64 pairs.
__global__ void detect_kernel(const int* __restrict__ coords) {
    int is64 = 1;
    #pragma unroll 8
    for (int i = 0; i < 64; i++) {
        if (coords[2 * i + 1] != 0) { is64 = 0; break; }
    }
    g_is64 = is64;
}

__global__ void init_idx_kernel() {
    int i = blockIdx.x * blockDim.x + threadIdx.x;
    if (i < Bc * NYc * NXc) g_idx[i] = -1;
}

__global__ void scatter_idx_kernel(const int* __restrict__ coords, int P) {
    int p = blockIdx.x * blockDim.x + threadIdx.x;
    if (p >= P) return;
    int x, y, b;
    if (g_is64) {
        const long long* c64 = (const long long*)coords;
        x = (int)c64[3 * p + 0];
        y = (int)c64[3 * p + 1];
        b = (int)c64[3 * p + 2];
    } else {
        x = coords[3 * p + 0];
        y = coords[3 * p + 1];
        b = coords[3 * p + 2];
    }
    g_idx[(b * NYc + y) * NXc + x] = p;
}

// One CTA per (b, y, x-tile). Gather pillar feature rows (contiguous 256B each,
// read exactly once) into SMEM transposed as [c][x] with padded stride 217
// (odd -> conflict-free for the strided write phase AND the coalesced read
// phase), then stream all 64 channel planes out with coalesced stores.
constexpr int TX   = 216;       // 432 = 2 * 216
constexpr int SROW = TX + 1;    // 217, gcd(217,32)=1 -> no bank conflicts

__global__ __launch_bounds__(256)
void gather_write_kernel(const float* __restrict__ feat, float* __restrict__ out) {
    extern __shared__ float sfeat[];   // Cc * SROW floats = 55,552 B
    __shared__ int sidx[TX];

    const int tile = blockIdx.x;   // 0..1
    const int y    = blockIdx.y;   // 0..495
    const int b    = blockIdx.z;   // 0..3
    const int x0   = tile * TX;
    const int tid  = threadIdx.x;

    if (tid < TX) sidx[tid] = g_idx[(b * NYc + y) * NXc + x0 + tid];
    __syncthreads();

    const int warp = tid >> 5;
    const int lane = tid & 31;

    // Gather phase: one warp per pillar slot; lanes cover channels 0..31 and
    // 32..63 via two coalesced 128B loads of the contiguous feature row.
    for (int xi = warp; xi < TX; xi += 8) {
        int p = sidx[xi];
        float v0 = 0.0f, v1 = 0.0f;
        if (p >= 0) {
            const float* f = feat + (size_t)p * Cc;
            v0 = f[lane];
            v1 = f[lane + 32];
        }
        sfeat[lane * SROW + xi]        = v0;
        sfeat[(lane + 32) * SROW + xi] = v1;
    }
    __syncthreads();

    // Write phase: thread tid = x within tile; 64 coalesced plane-row stores.
    if (tid < TX) {
        size_t base = (((size_t)b * Cc) * NYc + y) * (size_t)NXc + x0 + tid;
        #pragma unroll 8
        for (int c = 0; c < Cc; c++) {
            out[base + (size_t)c * (NYc * NXc)] = sfeat[c * SROW + tid];
        }
    }
}

extern "C" void kernel_launch(void* const* d_in, const int* in_sizes, int n_in,
                              void* d_out, int out_size) {
    const float* feat   = (const float*)d_in[0];          // [P, 64] fp32
    const int*   coords = (const int*)d_in[1];            // [P, 3] int32 or int64
    float*       out    = (float*)d_out;                  // [B, C, NY, NX] fp32

    const int P = in_sizes[0] / Cc;

    // Opt in to >48KB dynamic SMEM (idempotent, host-side, capture-safe).
    cudaFuncSetAttribute(gather_write_kernel,
                         cudaFuncAttributeMaxDynamicSharedMemorySize,
                         Cc * SROW * (int)sizeof(float));

    detect_kernel<<<1, 1>>>(coords);

    const int ncells = Bc * NYc * NXc;
    init_idx_kernel<<<(ncells + 255) / 256, 256>>>();

    scatter_idx_kernel<<<(P + 255) / 256, 256>>>(coords, P);

    dim3 grid(NXc / TX, NYc, Bc);   // (2, 496, 4) = 3968 CTAs
    gather_write_kernel<<<grid, 256, Cc * SROW * sizeof(float)>>>(feat, out);
}